// round 4
// baseline (speedup 1.0000x reference)
#include <cuda_runtime.h>
#include <cuda_bf16.h>
#include <cstdint>

// Problem constants
#define VOCAB   100000
#define EMBED   128
#define BATCH   64
#define SEQLEN  2048
#define NCHUNK  16
#define CHUNK   (SEQLEN / NCHUNK)   // 128 tokens per accumulate block

// Device scratch (no allocations allowed anywhere).
__device__ int   g_is64;                    // 1 if x buffer is int64, 0 if int32
__device__ int   g_toks[BATCH * SEQLEN];    // normalized token ids (int32, clamped)
__device__ float g_sums[BATCH * EMBED];     // per-batch full embedding sum

// ---------------------------------------------------------------------------
// Kernel 0: dtype detect. If the first 32 values interpreted as int64 are all
// valid token ids, the buffer really is int64. Reinterpreted int32 data makes
// huge values (hi word is a random token) with overwhelming probability.
// ---------------------------------------------------------------------------
__global__ void cbow_detect_kernel(const void* __restrict__ x) {
    const long long* p = (const long long*)x;
    int ok = 1;
    #pragma unroll
    for (int i = 0; i < 32; i++) {
        long long v = p[i];
        if (v < 0 || v >= VOCAB) { ok = 0; break; }
    }
    g_is64 = ok;
}

// ---------------------------------------------------------------------------
// Kernel 1: convert tokens to int32 (clamped -> no possible OOB gather later)
// and zero the accumulator scratch. grid covers BATCH*SEQLEN threads.
// ---------------------------------------------------------------------------
__global__ __launch_bounds__(256) void cbow_convert_zero_kernel(const void* __restrict__ x) {
    const int i = blockIdx.x * blockDim.x + threadIdx.x;
    const int is64 = g_is64;  // uniform
    if (i < BATCH * SEQLEN) {
        long long v = is64 ? ((const long long*)x)[i]
                           : (long long)((const int*)x)[i];
        if (v < 0) v = 0;
        if (v >= VOCAB) v = VOCAB - 1;
        g_toks[i] = (int)v;
    }
    if (i < BATCH * EMBED) g_sums[i] = 0.0f;
}

// ---------------------------------------------------------------------------
// Kernel 2: accumulate S_b = sum over a CHUNK of tokens of emb[tok].
// grid = (NCHUNK, BATCH), block = 128.
// lane c = tid&31 owns float4 column c of the 128-float row (32x16B = 512B,
// fully coalesced per row); group g = tid>>5 phases over tokens by 4.
// ---------------------------------------------------------------------------
__global__ __launch_bounds__(128) void cbow_accum_kernel(
    const float* __restrict__ emb)     // [VOCAB, EMBED] f32
{
    __shared__ int    toks[CHUNK];
    __shared__ float4 part[128];

    const int b    = blockIdx.y;
    const int base = blockIdx.x * CHUNK;
    const int tid  = threadIdx.x;

    if (tid < CHUNK) {
        toks[tid] = g_toks[b * SEQLEN + base + tid];
    }
    __syncthreads();

    const int c = tid & 31;   // float4 column within the row
    const int g = tid >> 5;   // token phase (0..3)

    float4 acc = make_float4(0.f, 0.f, 0.f, 0.f);

    #pragma unroll 8
    for (int t = g; t < CHUNK; t += 4) {
        const float4 v = __ldg(reinterpret_cast<const float4*>(
            emb + (size_t)toks[t] * EMBED) + c);
        acc.x += v.x; acc.y += v.y; acc.z += v.z; acc.w += v.w;
    }

    part[tid] = acc;
    __syncthreads();

    if (g == 0) {
        float4 p0 = part[c];
        float4 p1 = part[32 + c];
        float4 p2 = part[64 + c];
        float4 p3 = part[96 + c];
        float sx = p0.x + p1.x + p2.x + p3.x;
        float sy = p0.y + p1.y + p2.y + p3.y;
        float sz = p0.z + p1.z + p2.z + p3.z;
        float sw = p0.w + p1.w + p2.w + p3.w;
        float* dst = &g_sums[b * EMBED + c * 4];
        atomicAdd(dst + 0, sx);
        atomicAdd(dst + 1, sy);
        atomicAdd(dst + 2, sz);
        atomicAdd(dst + 3, sw);
    }
}

// ---------------------------------------------------------------------------
// Kernel 3: finalize. Output layout [B, 2C=4, E], offset order [-1,-2,+1,+2]
// (matches reference concatenate(-arange(1..C), +arange(1..C))).
//   off -1: S - emb[x[L-1]]               + 1*emb[0]
//   off -2: S - emb[x[L-1]] - emb[x[L-2]] + 2*emb[0]
//   off +1: S - emb[x[0]]                 + 1*emb[0]
//   off +2: S - emb[x[0]]   - emb[x[1]]   + 2*emb[0]
// ---------------------------------------------------------------------------
__global__ __launch_bounds__(128) void cbow_finalize_kernel(
    const float* __restrict__ emb,
    float* __restrict__ out)
{
    const int b = blockIdx.x;
    const int e = threadIdx.x;

    const float S  = g_sums[b * EMBED + e];
    const float e0 = emb[e];  // emb[token 0]

    const int tf0 = g_toks[b * SEQLEN + 0];
    const int tf1 = g_toks[b * SEQLEN + 1];
    const int tl0 = g_toks[b * SEQLEN + (SEQLEN - 1)];
    const int tl1 = g_toks[b * SEQLEN + (SEQLEN - 2)];

    const float f0 = emb[(size_t)tf0 * EMBED + e];
    const float f1 = emb[(size_t)tf1 * EMBED + e];
    const float l0 = emb[(size_t)tl0 * EMBED + e];
    const float l1 = emb[(size_t)tl1 * EMBED + e];

    float* o = out + (size_t)b * 4 * EMBED;
    o[0 * EMBED + e] = S - l0 + e0;                  // offset -1
    o[1 * EMBED + e] = S - l0 - l1 + 2.0f * e0;      // offset -2
    o[2 * EMBED + e] = S - f0 + e0;                  // offset +1
    o[3 * EMBED + e] = S - f0 - f1 + 2.0f * e0;      // offset +2
}

// ---------------------------------------------------------------------------
// Launch. Input order resolved from element counts:
//   x   : BATCH*SEQLEN   = 131072 elements
//   emb : VOCAB*EMBED    = 12800000 elements
// Output: float32, BATCH*4*EMBED = 32768 elements.
// ---------------------------------------------------------------------------
extern "C" void kernel_launch(void* const* d_in, const int* in_sizes, int n_in,
                              void* d_out, int out_size) {
    int ix = 0, ie = 1;
    if (in_sizes[0] != BATCH * SEQLEN) { ix = 1; ie = 0; }

    const void*  x   = d_in[ix];
    const float* emb = (const float*)d_in[ie];
    float*       out = (float*)d_out;

    cbow_detect_kernel<<<1, 1>>>(x);

    cbow_convert_zero_kernel<<<(BATCH * SEQLEN + 255) / 256, 256>>>(x);

    dim3 grid(NCHUNK, BATCH);
    cbow_accum_kernel<<<grid, 128>>>(emb);

    cbow_finalize_kernel<<<BATCH, 128>>>(emb, out);
}

// round 5
// speedup vs baseline: 1.1059x; 1.1059x over previous
#include <cuda_runtime.h>
#include <cuda_bf16.h>
#include <cstdint>

// Problem constants
#define VOCAB   100000
#define EMBED   128
#define BATCH   64
#define SEQLEN  2048
#define NCHUNK  16
#define CHUNK   (SEQLEN / NCHUNK)   // 128 tokens per block

// Device scratch (zero-initialized at load; every kernel execution restores
// the all-zero invariant, so graph replays are deterministic).
__device__ float g_sums[BATCH * EMBED];
__device__ int   g_count[BATCH];

// ---------------------------------------------------------------------------
// Single fused kernel.
// grid = (NCHUNK, BATCH), block = 128 threads.
//
// Phase 0: dtype detect (per block, from the first 32 int64-interpreted words
//          of x — in-bounds under both dtypes, broadcast from L2).
// Phase 1: stage this chunk's 128 tokens into smem (converted to int, clamped).
// Phase 2: gather-accumulate emb rows. lane c = tid&31 owns float4 column c
//          (32 lanes x 16B = 512B per row, fully coalesced); group g = tid>>5
//          phases over tokens by 4; unroll 8 for MLP.
// Phase 3: cross-phase reduce in smem, atomicAdd into g_sums[b].
// Phase 4: last block per batch (completion counter) computes the 4 outputs
//          from the full-sequence sum + boundary corrections, then resets
//          the scratch for the next graph replay.
//
// Output layout [B, 2C=4, E], offset order [-1,-2,+1,+2]:
//   off -1: S - emb[x[L-1]]               + 1*emb[0]
//   off -2: S - emb[x[L-1]] - emb[x[L-2]] + 2*emb[0]
//   off +1: S - emb[x[0]]                 + 1*emb[0]
//   off +2: S - emb[x[0]]   - emb[x[1]]   + 2*emb[0]
// ---------------------------------------------------------------------------
__global__ __launch_bounds__(128) void cbow_fused_kernel(
    const void* __restrict__ xraw,     // [BATCH, SEQLEN] token ids (int64 or int32)
    const float* __restrict__ emb,     // [VOCAB, EMBED] f32
    float* __restrict__ out)           // [BATCH, 4, EMBED] f32
{
    __shared__ int    toks[CHUNK];
    __shared__ float4 part[128];
    __shared__ int    s_is64;
    __shared__ int    s_last;

    const int b    = blockIdx.y;
    const int base = blockIdx.x * CHUNK;
    const int tid  = threadIdx.x;

    // ---- Phase 0: dtype detection (warp 0) ----
    if (tid < 32) {
        const long long v = ((const long long*)xraw)[tid];  // first 256B: in-bounds always
        const unsigned bad = __ballot_sync(0xFFFFFFFFu, v < 0 || v >= VOCAB);
        if (tid == 0) s_is64 = (bad == 0u);
    }
    __syncthreads();
    const int is64 = s_is64;

    // ---- Phase 1: stage tokens ----
    {
        const int idx = b * SEQLEN + base + tid;
        long long v = is64 ? ((const long long*)xraw)[idx]
                           : (long long)((const int*)xraw)[idx];
        if (v < 0) v = 0;
        if (v >= VOCAB) v = VOCAB - 1;
        toks[tid] = (int)v;
    }
    __syncthreads();

    // ---- Phase 2: gather-accumulate ----
    const int c = tid & 31;   // float4 column within the 128-float row
    const int g = tid >> 5;   // token phase (0..3)

    float4 acc = make_float4(0.f, 0.f, 0.f, 0.f);
    #pragma unroll 8
    for (int t = g; t < CHUNK; t += 4) {
        const float4 v = __ldg(reinterpret_cast<const float4*>(
            emb + (size_t)toks[t] * EMBED) + c);
        acc.x += v.x; acc.y += v.y; acc.z += v.z; acc.w += v.w;
    }
    part[tid] = acc;
    __syncthreads();

    // ---- Phase 3: reduce 4 phases, atomic into per-batch sum ----
    if (g == 0) {
        const float4 p0 = part[c];
        const float4 p1 = part[32 + c];
        const float4 p2 = part[64 + c];
        const float4 p3 = part[96 + c];
        float* dst = &g_sums[b * EMBED + c * 4];
        atomicAdd(dst + 0, p0.x + p1.x + p2.x + p3.x);
        atomicAdd(dst + 1, p0.y + p1.y + p2.y + p3.y);
        atomicAdd(dst + 2, p0.z + p1.z + p2.z + p3.z);
        atomicAdd(dst + 3, p0.w + p1.w + p2.w + p3.w);
    }

    // Make our atomics visible device-wide before signalling completion.
    __threadfence();
    __syncthreads();
    if (tid == 0) {
        const int old = atomicAdd(&g_count[b], 1);
        s_last = (old == NCHUNK - 1);
    }
    __syncthreads();

    // ---- Phase 4: last block of this batch finalizes ----
    if (s_last) {
        const int e = tid;

        // Volatile read: bypasses any stale L1 line; atomics land in L2.
        const float S = *(volatile float*)&g_sums[b * EMBED + e];

        // Boundary tokens for this batch row (dtype-aware).
        long long tf0, tf1, tl0, tl1;
        if (is64) {
            const long long* x64 = (const long long*)xraw;
            tf0 = x64[(size_t)b * SEQLEN + 0];
            tf1 = x64[(size_t)b * SEQLEN + 1];
            tl1 = x64[(size_t)b * SEQLEN + (SEQLEN - 2)];
            tl0 = x64[(size_t)b * SEQLEN + (SEQLEN - 1)];
        } else {
            const int* x32 = (const int*)xraw;
            tf0 = x32[(size_t)b * SEQLEN + 0];
            tf1 = x32[(size_t)b * SEQLEN + 1];
            tl1 = x32[(size_t)b * SEQLEN + (SEQLEN - 2)];
            tl0 = x32[(size_t)b * SEQLEN + (SEQLEN - 1)];
        }
        if (tf0 < 0) tf0 = 0; if (tf0 >= VOCAB) tf0 = VOCAB - 1;
        if (tf1 < 0) tf1 = 0; if (tf1 >= VOCAB) tf1 = VOCAB - 1;
        if (tl0 < 0) tl0 = 0; if (tl0 >= VOCAB) tl0 = VOCAB - 1;
        if (tl1 < 0) tl1 = 0; if (tl1 >= VOCAB) tl1 = VOCAB - 1;

        const float e0 = emb[e];  // emb[token 0][e]
        const float f0 = emb[(size_t)tf0 * EMBED + e];
        const float f1 = emb[(size_t)tf1 * EMBED + e];
        const float l0 = emb[(size_t)tl0 * EMBED + e];
        const float l1 = emb[(size_t)tl1 * EMBED + e];

        float* o = out + (size_t)b * 4 * EMBED;
        o[0 * EMBED + e] = S - l0 + e0;                  // offset -1
        o[1 * EMBED + e] = S - l0 - l1 + 2.0f * e0;      // offset -2
        o[2 * EMBED + e] = S - f0 + e0;                  // offset +1
        o[3 * EMBED + e] = S - f0 - f1 + 2.0f * e0;      // offset +2

        // Restore the zero-invariant for the next graph replay.
        g_sums[b * EMBED + e] = 0.0f;
        if (tid == 0) g_count[b] = 0;
    }
}

// ---------------------------------------------------------------------------
// Launch. Input order resolved from element counts:
//   x   : BATCH*SEQLEN = 131072 elements
//   emb : VOCAB*EMBED  = 12800000 elements
// ---------------------------------------------------------------------------
extern "C" void kernel_launch(void* const* d_in, const int* in_sizes, int n_in,
                              void* d_out, int out_size) {
    int ix = 0, ie = 1;
    if (in_sizes[0] != BATCH * SEQLEN) { ix = 1; ie = 0; }

    const void*  x   = d_in[ix];
    const float* emb = (const float*)d_in[ie];
    float*       out = (float*)d_out;

    dim3 grid(NCHUNK, BATCH);
    cbow_fused_kernel<<<grid, 128>>>(x, emb, out);
}

// round 6
// speedup vs baseline: 1.1114x; 1.0050x over previous
#include <cuda_runtime.h>
#include <cuda_bf16.h>
#include <cstdint>

// Problem constants
#define VOCAB   100000
#define EMBED   128
#define BATCH   64
#define SEQLEN  2048
#define NCHUNK  32
#define CHUNK   (SEQLEN / NCHUNK)   // 64 tokens per block

// Device scratch (zero-initialized at load; every kernel execution restores
// the all-zero invariant, so graph replays are deterministic).
__device__ float g_sums[BATCH * EMBED];
__device__ int   g_count[BATCH];

// ---------------------------------------------------------------------------
// Single fused kernel.
// grid = (NCHUNK, BATCH) = (32, 64) = 2048 blocks, block = 128 threads.
// -> 8192 warps over 148 SMs = ~86% occupancy in a single wave (the R5
//    profile showed occupancy capped at 43% purely by grid size).
//
// Phase 0: dtype detect (first 32 int64-interpreted words of x; in-bounds
//          under both dtypes, L2-broadcast).
// Phase 1: stage this chunk's 64 tokens into smem (int, clamped).
// Phase 2: gather-accumulate emb rows. lane c = tid&31 owns float4 column c
//          (32 lanes x 16B = 512B/row, coalesced); group g = tid>>5 phases
//          tokens by 4; 16 fully-unrolled independent loads -> MLP ~16.
// Phase 3: smem cross-phase reduce, atomicAdd into g_sums[b].
// Phase 4: last block per batch finalizes: full-sum + boundary corrections,
//          writes out, resets scratch for the next graph replay.
//
// Output layout [B, 2C=4, E], offset order [-1,-2,+1,+2]:
//   off -1: S - emb[x[L-1]]               + 1*emb[0]
//   off -2: S - emb[x[L-1]] - emb[x[L-2]] + 2*emb[0]
//   off +1: S - emb[x[0]]                 + 1*emb[0]
//   off +2: S - emb[x[0]]   - emb[x[1]]   + 2*emb[0]
// ---------------------------------------------------------------------------
__global__ __launch_bounds__(128) void cbow_fused_kernel(
    const void* __restrict__ xraw,     // [BATCH, SEQLEN] token ids (int64 or int32)
    const float* __restrict__ emb,     // [VOCAB, EMBED] f32
    float* __restrict__ out)           // [BATCH, 4, EMBED] f32
{
    __shared__ int    toks[CHUNK];
    __shared__ float4 part[128];
    __shared__ int    s_is64;
    __shared__ int    s_last;

    const int b    = blockIdx.y;
    const int base = blockIdx.x * CHUNK;
    const int tid  = threadIdx.x;

    // ---- Phase 0: dtype detection (warp 0) ----
    if (tid < 32) {
        const long long v = ((const long long*)xraw)[tid];  // first 256B: safe both dtypes
        const unsigned bad = __ballot_sync(0xFFFFFFFFu, v < 0 || v >= VOCAB);
        if (tid == 0) s_is64 = (bad == 0u);
    }
    __syncthreads();
    const int is64 = s_is64;

    // ---- Phase 1: stage tokens (CHUNK=64 -> first 64 threads) ----
    if (tid < CHUNK) {
        const int idx = b * SEQLEN + base + tid;
        long long v = is64 ? ((const long long*)xraw)[idx]
                           : (long long)((const int*)xraw)[idx];
        if (v < 0) v = 0;
        if (v >= VOCAB) v = VOCAB - 1;
        toks[tid] = (int)v;
    }
    __syncthreads();

    // ---- Phase 2: gather-accumulate (16 independent loads, fully unrolled) ----
    const int c = tid & 31;   // float4 column within the 128-float row
    const int g = tid >> 5;   // token phase (0..3)

    float4 acc = make_float4(0.f, 0.f, 0.f, 0.f);
    #pragma unroll
    for (int t = g; t < CHUNK; t += 4) {
        const float4 v = __ldg(reinterpret_cast<const float4*>(
            emb + (size_t)toks[t] * EMBED) + c);
        acc.x += v.x; acc.y += v.y; acc.z += v.z; acc.w += v.w;
    }
    part[tid] = acc;
    __syncthreads();

    // ---- Phase 3: reduce the 4 token phases, atomic into per-batch sum ----
    if (g == 0) {
        const float4 p0 = part[c];
        const float4 p1 = part[32 + c];
        const float4 p2 = part[64 + c];
        const float4 p3 = part[96 + c];
        float* dst = &g_sums[b * EMBED + c * 4];
        atomicAdd(dst + 0, p0.x + p1.x + p2.x + p3.x);
        atomicAdd(dst + 1, p0.y + p1.y + p2.y + p3.y);
        atomicAdd(dst + 2, p0.z + p1.z + p2.z + p3.z);
        atomicAdd(dst + 3, p0.w + p1.w + p2.w + p3.w);
    }

    // Make our atomics visible device-wide before signalling completion.
    __threadfence();
    __syncthreads();
    if (tid == 0) {
        const int old = atomicAdd(&g_count[b], 1);
        s_last = (old == NCHUNK - 1);
    }
    __syncthreads();

    // ---- Phase 4: last block of this batch finalizes ----
    if (s_last) {
        const int e = tid;

        // Volatile read: atomics land in L2; bypass any stale L1 line.
        const float S = *(volatile float*)&g_sums[b * EMBED + e];

        // Boundary tokens for this batch row (dtype-aware).
        long long tf0, tf1, tl0, tl1;
        if (is64) {
            const long long* x64 = (const long long*)xraw;
            tf0 = x64[(size_t)b * SEQLEN + 0];
            tf1 = x64[(size_t)b * SEQLEN + 1];
            tl1 = x64[(size_t)b * SEQLEN + (SEQLEN - 2)];
            tl0 = x64[(size_t)b * SEQLEN + (SEQLEN - 1)];
        } else {
            const int* x32 = (const int*)xraw;
            tf0 = x32[(size_t)b * SEQLEN + 0];
            tf1 = x32[(size_t)b * SEQLEN + 1];
            tl1 = x32[(size_t)b * SEQLEN + (SEQLEN - 2)];
            tl0 = x32[(size_t)b * SEQLEN + (SEQLEN - 1)];
        }
        if (tf0 < 0) tf0 = 0; if (tf0 >= VOCAB) tf0 = VOCAB - 1;
        if (tf1 < 0) tf1 = 0; if (tf1 >= VOCAB) tf1 = VOCAB - 1;
        if (tl0 < 0) tl0 = 0; if (tl0 >= VOCAB) tl0 = VOCAB - 1;
        if (tl1 < 0) tl1 = 0; if (tl1 >= VOCAB) tl1 = VOCAB - 1;

        const float e0 = emb[e];  // emb[token 0][e]
        const float f0 = emb[(size_t)tf0 * EMBED + e];
        const float f1 = emb[(size_t)tf1 * EMBED + e];
        const float l0 = emb[(size_t)tl0 * EMBED + e];
        const float l1 = emb[(size_t)tl1 * EMBED + e];

        float* o = out + (size_t)b * 4 * EMBED;
        o[0 * EMBED + e] = S - l0 + e0;                  // offset -1
        o[1 * EMBED + e] = S - l0 - l1 + 2.0f * e0;      // offset -2
        o[2 * EMBED + e] = S - f0 + e0;                  // offset +1
        o[3 * EMBED + e] = S - f0 - f1 + 2.0f * e0;      // offset +2

        // Restore the zero-invariant for the next graph replay.
        g_sums[b * EMBED + e] = 0.0f;
        if (tid == 0) g_count[b] = 0;
    }
}

// ---------------------------------------------------------------------------
// Launch. Input order resolved from element counts:
//   x   : BATCH*SEQLEN = 131072 elements
//   emb : VOCAB*EMBED  = 12800000 elements
// ---------------------------------------------------------------------------
extern "C" void kernel_launch(void* const* d_in, const int* in_sizes, int n_in,
                              void* d_out, int out_size) {
    int ix = 0, ie = 1;
    if (in_sizes[0] != BATCH * SEQLEN) { ix = 1; ie = 0; }

    const void*  x   = d_in[ix];
    const float* emb = (const float*)d_in[ie];
    float*       out = (float*)d_out;

    dim3 grid(NCHUNK, BATCH);
    cbow_fused_kernel<<<grid, 128>>>(x, emb, out);
}